// round 15
// baseline (speedup 1.0000x reference)
#include <cuda_runtime.h>
#include <cuda_fp16.h>
#include <math.h>

#define NN 100000
#define NE 3200000
#define EK_BLOCKS 3125   // 3125 blocks * 8 warps * 128 edges/warp = 3.2M

// Scratch (device globals; zero-init at load; every invocation restores zeros
// => deterministic under graph replay)
__device__ float    g_deg[NN];
__device__ double   g_sum;
__device__ unsigned g_done;
__device__ __align__(16) __half g_ynorm[NN * 16];   // y * rsqrt(degree), 32B/row

// Per-warp dtype detect: int64 < 100000 => odd 32-bit words all zero.
__device__ __forceinline__ int detect_is64(const void* ei) {
    int lane = threadIdx.x & 31;
    unsigned v = ((const unsigned*)ei)[2 * lane + 1];
    return __ballot_sync(0xffffffffu, v == 0u) == 0xffffffffu;
}

// ---------------------------------------------------------------------------
// Kernel 1: degree = segment_sum(edge_weights, row). 2 edges/thread
// (measured-best across 2/4/8 sweep: LTS atomic pipe is the floor).
// ---------------------------------------------------------------------------
__global__ void degree_kernel(const void* __restrict__ ei,
                              const float2* __restrict__ w2) {
    int is64 = detect_is64(ei);
    int t = blockIdx.x * blockDim.x + threadIdx.x;   // grid = NE/2 threads
    float2 w = w2[t];
    int r0, r1;
    if (is64) {
        longlong2 a = ((const longlong2*)ei)[t];
        r0 = (int)a.x; r1 = (int)a.y;
    } else {
        int2 a = ((const int2*)ei)[t];
        r0 = a.x; r1 = a.y;
    }
    atomicAdd(&g_deg[r0], w.x);
    atomicAdd(&g_deg[r1], w.y);
    cudaTriggerProgrammaticLaunchCompletion();       // let ynorm launch early
}

// ---------------------------------------------------------------------------
// Kernel 2 (PDL): y reads overlap degree's tail; sync guards g_deg read only.
// ---------------------------------------------------------------------------
__global__ void ynorm_kernel(const float4* __restrict__ y) {
    int i = blockIdx.x * blockDim.x + threadIdx.x;
    float4 v[4];
    if (i < NN) {
        #pragma unroll
        for (int k = 0; k < 4; k++) v[k] = y[i * 4 + k];   // independent of g_deg
    }
    cudaGridDependencySynchronize();                        // wait for degree
    if (i < NN) {
        float dinv = rsqrtf(g_deg[i]);
        g_deg[i] = 0.0f;                                    // restore invariant
        __half2* o = (__half2*)(g_ynorm + (size_t)i * 16);
        #pragma unroll
        for (int k = 0; k < 4; k++) {
            o[2 * k]     = __floats2half2_rn(v[k].x * dinv, v[k].y * dinv);
            o[2 * k + 1] = __floats2half2_rn(v[k].z * dinv, v[k].w * dinv);
        }
    }
    cudaTriggerProgrammaticLaunchCompletion();              // let edge launch
}

// ---------------------------------------------------------------------------
// Kernel 3 (PDL): per-edge weighted L2 of ynorm[r]-ynorm[c] -> mean in d_out.
// 1 lane per edge, 4 consecutive edges per lane: metadata loaded once (no
// lane-pair duplication), zero SHFLs in the accumulate chain. Metadata loads
// run BEFORE the dependency sync (overlap with ynorm). Last block finalizes.
// ---------------------------------------------------------------------------
__global__ void __launch_bounds__(256)
edge_kernel(const void* __restrict__ ei, const float* __restrict__ w,
            float* __restrict__ out) {
    int is64   = detect_is64(ei);
    int tid    = blockIdx.x * blockDim.x + threadIdx.x;
    int lane   = threadIdx.x & 31;
    int e0     = tid * 4;                 // 4 consecutive edges per lane
    const uint4* yn = (const uint4*)g_ynorm;

    // Phase 1: vectorized index + weight loads (independent of g_ynorm)
    int r[4], c[4];
    if (is64) {
        const longlong2* pr = (const longlong2*)ei + (e0 >> 1);
        const longlong2* pc = (const longlong2*)ei + ((NE + e0) >> 1);
        #pragma unroll
        for (int k = 0; k < 2; k++) {
            longlong2 a = pr[k];
            longlong2 b = pc[k];
            r[2 * k] = (int)a.x; r[2 * k + 1] = (int)a.y;
            c[2 * k] = (int)b.x; c[2 * k + 1] = (int)b.y;
        }
    } else {
        int4 a = ((const int4*)ei)[e0 >> 2];
        int4 b = ((const int4*)ei)[(NE + e0) >> 2];
        r[0] = a.x; r[1] = a.y; r[2] = a.z; r[3] = a.w;
        c[0] = b.x; c[1] = b.y; c[2] = b.z; c[3] = b.w;
    }
    float4 wv4 = *(const float4*)(w + e0);
    float wv[4] = {wv4.x, wv4.y, wv4.z, wv4.w};

    cudaGridDependencySynchronize();                        // wait for ynorm

    // Phase 2: gathers + half2 compute, no cross-lane traffic
    float acc = 0.0f;
    #pragma unroll
    for (int j = 0; j < 4; j++) {
        uint4 hr0 = __ldg(yn + r[j] * 2);
        uint4 hr1 = __ldg(yn + r[j] * 2 + 1);
        uint4 hc0 = __ldg(yn + c[j] * 2);
        uint4 hc1 = __ldg(yn + c[j] * 2 + 1);
        const __half2* a0 = (const __half2*)&hr0;
        const __half2* a1 = (const __half2*)&hr1;
        const __half2* b0 = (const __half2*)&hc0;
        const __half2* b1 = (const __half2*)&hc1;
        __half2 s2 = __float2half2_rn(0.0f);
        #pragma unroll
        for (int k = 0; k < 4; k++) {
            __half2 d0 = __hsub2(a0[k], b0[k]);
            __half2 d1 = __hsub2(a1[k], b1[k]);
            s2 = __hfma2(d0, d0, s2);
            s2 = __hfma2(d1, d1, s2);
        }
        float s = __low2float(s2) + __high2float(s2);
        acc += sqrtf(s) * wv[j];
    }

    // Block reduction + last-block finalize
    #pragma unroll
    for (int off = 16; off; off >>= 1)
        acc += __shfl_down_sync(0xffffffffu, acc, off);
    __shared__ float warp_sums[8];
    int wid = threadIdx.x >> 5;
    if (lane == 0) warp_sums[wid] = acc;
    __syncthreads();
    if (wid == 0) {
        float v = (lane < 8) ? warp_sums[lane] : 0.0f;
        #pragma unroll
        for (int off = 4; off; off >>= 1)
            v += __shfl_down_sync(0xffffffffu, v, off);
        if (lane == 0) {
            atomicAdd(&g_sum, (double)v);
            __threadfence();
            unsigned ticket = atomicAdd(&g_done, 1u);
            if (ticket == EK_BLOCKS - 1) {            // last block: finalize
                out[0] = (float)(g_sum / (double)NE);
                g_sum  = 0.0;                          // restore invariants
                g_done = 0u;
                __threadfence();
            }
        }
    }
}

// Helper: PDL launch. If the attribute/trigger is ignored, launches serialize
// normally and the device-side sync returns immediately -> still correct.
template <typename K, typename... Args>
static void launch_pdl(K kernel, dim3 grid, dim3 block, Args... args) {
    cudaLaunchConfig_t cfg = {};
    cfg.gridDim  = grid;
    cfg.blockDim = block;
    cudaLaunchAttribute attr[1];
    attr[0].id = cudaLaunchAttributeProgrammaticStreamSerialization;
    attr[0].val.programmaticStreamSerializationAllowed = 1;
    cfg.attrs    = attr;
    cfg.numAttrs = 1;
    cudaLaunchKernelEx(&cfg, kernel, args...);
}

extern "C" void kernel_launch(void* const* d_in, const int* in_sizes, int n_in,
                              void* d_out, int out_size) {
    const void*  ei = d_in[0];                  // edge_index (2, NE)
    const float* w  = (const float*)d_in[1];    // edge_weights (NE,)
    const float* y  = (const float*)d_in[2];    // y (NN, 16)

    degree_kernel<<<NE / 2 / 256, 256>>>(ei, (const float2*)w);
    launch_pdl(ynorm_kernel, dim3((NN + 255) / 256), dim3(256),
               (const float4*)y);
    launch_pdl(edge_kernel, dim3(EK_BLOCKS), dim3(256),
               ei, w, (float*)d_out);
}

// round 16
// speedup vs baseline: 1.1244x; 1.1244x over previous
#include <cuda_runtime.h>
#include <cuda_fp16.h>
#include <math.h>

#define NN 100000
#define NE 3200000
#define EK_BLOCKS 3125   // 3125 blocks * 8 warps * 128 edges/warp = 3.2M

// Scratch (device globals; zero-init at load; every invocation restores zeros
// => deterministic under graph replay)
__device__ float    g_deg[NN];
__device__ double   g_sum;
__device__ unsigned g_done;
__device__ __align__(16) __half g_ynorm[NN * 16];   // y * rsqrt(degree), 32B/row

// Per-warp dtype detect: int64 < 100000 => odd 32-bit words all zero.
__device__ __forceinline__ int detect_is64(const void* ei) {
    int lane = threadIdx.x & 31;
    unsigned v = ((const unsigned*)ei)[2 * lane + 1];
    return __ballot_sync(0xffffffffu, v == 0u) == 0xffffffffu;
}

// ---------------------------------------------------------------------------
// Kernel 1: degree = segment_sum(edge_weights, row). 2 edges/thread
// (measured-best across 2/4/8 sweep: LTS atomic pipe is the floor).
// Trailing PDL trigger lets ynorm start its prologue while atomics drain.
// ---------------------------------------------------------------------------
__global__ void degree_kernel(const void* __restrict__ ei,
                              const float2* __restrict__ w2) {
    int is64 = detect_is64(ei);
    int t = blockIdx.x * blockDim.x + threadIdx.x;   // grid = NE/2 threads
    float2 w = w2[t];
    int r0, r1;
    if (is64) {
        longlong2 a = ((const longlong2*)ei)[t];
        r0 = (int)a.x; r1 = (int)a.y;
    } else {
        int2 a = ((const int2*)ei)[t];
        r0 = a.x; r1 = a.y;
    }
    atomicAdd(&g_deg[r0], w.x);
    atomicAdd(&g_deg[r1], w.y);
    cudaTriggerProgrammaticLaunchCompletion();       // let ynorm launch early
}

// ---------------------------------------------------------------------------
// Kernel 2 (PDL): y reads overlap degree's tail; sync guards g_deg read only.
// Trailing trigger lets edge_kernel stream its metadata while we finish.
// ---------------------------------------------------------------------------
__global__ void ynorm_kernel(const float4* __restrict__ y) {
    int i = blockIdx.x * blockDim.x + threadIdx.x;
    float4 v[4];
    if (i < NN) {
        #pragma unroll
        for (int k = 0; k < 4; k++) v[k] = y[i * 4 + k];   // independent of g_deg
    }
    cudaGridDependencySynchronize();                        // wait for degree
    if (i < NN) {
        float dinv = rsqrtf(g_deg[i]);
        g_deg[i] = 0.0f;                                    // restore invariant
        __half2* o = (__half2*)(g_ynorm + (size_t)i * 16);
        #pragma unroll
        for (int k = 0; k < 4; k++) {
            o[2 * k]     = __floats2half2_rn(v[k].x * dinv, v[k].y * dinv);
            o[2 * k + 1] = __floats2half2_rn(v[k].z * dinv, v[k].w * dinv);
        }
    }
    cudaTriggerProgrammaticLaunchCompletion();              // let edge launch
}

// ---------------------------------------------------------------------------
// Kernel 3 (PDL): per-edge weighted L2 of ynorm[r]-ynorm[c] -> mean in d_out.
// Lane pair (gid,sub) owns 8 consecutive edges; vectorized metadata loads
// run BEFORE the dependency sync (overlap with ynorm); __ldg gathers; half2
// diff/square; alternating sqrt lane. Last block finalizes in-kernel.
// ---------------------------------------------------------------------------
__global__ void __launch_bounds__(256)
edge_kernel(const void* __restrict__ ei, const float* __restrict__ w,
            float* __restrict__ out) {
    int is64   = detect_is64(ei);
    int tid    = blockIdx.x * blockDim.x + threadIdx.x;
    int warpId = tid >> 5;
    int lane   = threadIdx.x & 31;
    int gid    = lane >> 1;      // edge-group slot (16 per warp)
    int sub    = lane & 1;       // which 16B half of the 32B row
    int e0     = warpId * 128 + gid * 8;   // this lane-pair's 8 consecutive edges
    const uint4* yn = (const uint4*)g_ynorm;

    // Phase 1: vectorized index + weight loads (independent of g_ynorm)
    int r[8], c[8];
    if (is64) {
        const longlong2* pr = (const longlong2*)ei + (e0 >> 1);
        const longlong2* pc = (const longlong2*)ei + ((NE + e0) >> 1);
        #pragma unroll
        for (int k = 0; k < 4; k++) {
            longlong2 a = pr[k];
            longlong2 b = pc[k];
            r[2 * k] = (int)a.x; r[2 * k + 1] = (int)a.y;
            c[2 * k] = (int)b.x; c[2 * k + 1] = (int)b.y;
        }
    } else {
        const int4* pr = (const int4*)ei + (e0 >> 2);
        const int4* pc = (const int4*)ei + ((NE + e0) >> 2);
        #pragma unroll
        for (int k = 0; k < 2; k++) {
            int4 a = pr[k];
            int4 b = pc[k];
            r[4*k] = a.x; r[4*k+1] = a.y; r[4*k+2] = a.z; r[4*k+3] = a.w;
            c[4*k] = b.x; c[4*k+1] = b.y; c[4*k+2] = b.z; c[4*k+3] = b.w;
        }
    }
    float wv[8];
    {
        const float4* pw = (const float4*)(w + e0);
        float4 w0 = pw[0], w1 = pw[1];
        wv[0] = w0.x; wv[1] = w0.y; wv[2] = w0.z; wv[3] = w0.w;
        wv[4] = w1.x; wv[5] = w1.y; wv[6] = w1.z; wv[7] = w1.w;
    }

    cudaGridDependencySynchronize();                        // wait for ynorm

    // Phase 2+3: non-coherent gathers + half2 compute
    float acc = 0.0f;
    #pragma unroll
    for (int j = 0; j < 8; j++) {
        uint4 hr = __ldg(yn + (r[j] * 2 + sub));
        uint4 hc = __ldg(yn + (c[j] * 2 + sub));
        const __half2* a2 = (const __half2*)&hr;
        const __half2* b2 = (const __half2*)&hc;
        __half2 s2 = __float2half2_rn(0.0f);
        #pragma unroll
        for (int k = 0; k < 4; k++) {
            __half2 d = __hsub2(a2[k], b2[k]);
            s2 = __hfma2(d, d, s2);
        }
        float s = __low2float(s2) + __high2float(s2);
        s += __shfl_xor_sync(0xffffffffu, s, 1);
        if (sub == (j & 1)) acc += sqrtf(s) * wv[j];
    }

    // Block reduction + last-block finalize
    #pragma unroll
    for (int off = 16; off; off >>= 1)
        acc += __shfl_down_sync(0xffffffffu, acc, off);
    __shared__ float warp_sums[8];
    int wid = threadIdx.x >> 5;
    if (lane == 0) warp_sums[wid] = acc;
    __syncthreads();
    if (wid == 0) {
        float v = (lane < 8) ? warp_sums[lane] : 0.0f;
        #pragma unroll
        for (int off = 4; off; off >>= 1)
            v += __shfl_down_sync(0xffffffffu, v, off);
        if (lane == 0) {
            atomicAdd(&g_sum, (double)v);
            __threadfence();
            unsigned ticket = atomicAdd(&g_done, 1u);
            if (ticket == EK_BLOCKS - 1) {            // last block: finalize
                out[0] = (float)(g_sum / (double)NE);
                g_sum  = 0.0;                          // restore invariants
                g_done = 0u;
                __threadfence();
            }
        }
    }
}

// Helper: PDL launch. If the attribute/trigger is ignored, launches serialize
// normally and the device-side sync returns immediately -> still correct.
template <typename K, typename... Args>
static void launch_pdl(K kernel, dim3 grid, dim3 block, Args... args) {
    cudaLaunchConfig_t cfg = {};
    cfg.gridDim  = grid;
    cfg.blockDim = block;
    cudaLaunchAttribute attr[1];
    attr[0].id = cudaLaunchAttributeProgrammaticStreamSerialization;
    attr[0].val.programmaticStreamSerializationAllowed = 1;
    cfg.attrs    = attr;
    cfg.numAttrs = 1;
    cudaLaunchKernelEx(&cfg, kernel, args...);
}

extern "C" void kernel_launch(void* const* d_in, const int* in_sizes, int n_in,
                              void* d_out, int out_size) {
    const void*  ei = d_in[0];                  // edge_index (2, NE)
    const float* w  = (const float*)d_in[1];    // edge_weights (NE,)
    const float* y  = (const float*)d_in[2];    // y (NN, 16)

    degree_kernel<<<NE / 2 / 256, 256>>>(ei, (const float2*)w);
    launch_pdl(ynorm_kernel, dim3((NN + 255) / 256), dim3(256),
               (const float4*)y);
    launch_pdl(edge_kernel, dim3(EK_BLOCKS), dim3(256),
               ei, w, (float*)d_out);
}